// round 5
// baseline (speedup 1.0000x reference)
#include <cuda_runtime.h>
#include <math.h>

#define NN   4096
#define NG   64
#define MH   128
#define MU   64
#define NSP  10
#define EPSF 1e-5f

#define INV_H  0.08838834764831845f   /* 1/sqrt(128) */
#define INV_U  0.125f                 /* 1/sqrt(64)  */
#define INV_TP 0.0078125f             /* 1/sqrt(2*128*64) */
#define INV_SC 0.02795084971874737f   /* 1/sqrt(1280) */
#define ISQRT3 0.57735026918962576f

// ------------- static device scratch (no runtime allocation) -------------
static __device__ float g_hp0[NN * MH];
static __device__ float g_hp1[NN * MH * 3];
static __device__ float g_up0[NN * MU];
static __device__ float g_up1[NN * MU * 3];
static __device__ float g_A[(size_t)NN * 16384];
static __device__ float g_W0cat[16384 * 256];
static __device__ float g_Wt10t[64 * 16384];
static __device__ float g_z0p[(size_t)4 * NN * 256];
static __device__ float g_s[NN * MH];
static __device__ float g_g[NN * MH];
static __device__ float g_ta[(size_t)NN * 8192];
static __device__ float g_tb[(size_t)NN * 16384];
static __device__ float g_vmat[NN * MH * 3];
static __device__ float g_y0[NN * MH];
static __device__ float g_y1[NN * MH * 3];
static __device__ int   g_spi[NN];
static __device__ float g_mean0[NG];
static __device__ float g_rs0[NG];
static __device__ float g_rs1[NG];

// ------------- prep: W0cat = [Wt00 ; Wt11/sqrt3], Wt10 permute -------------
__global__ void k_prep(const float* __restrict__ Wt00, const float* __restrict__ Wt11,
                       const float* __restrict__ Wt10)
{
    const int S0 = 8192 * 256;          // Wt00 part
    const int S1 = 2 * S0;              // Wt11 part
    const int S2 = S1 + 64 * 16384;     // Wt10 permute
    int idx = blockIdx.x * blockDim.x + threadIdx.x;
    if (idx < S0) { g_W0cat[idx] = Wt00[idx]; return; }
    if (idx < S1) { g_W0cat[idx] = Wt11[idx - S0] * ISQRT3; return; }
    if (idx < S2) {
        int j = idx - S1;
        int v = j >> 14;
        int u = (j >> 7) & 127;
        int w = j & 127;
        g_Wt10t[j] = Wt10[(size_t)u * 8192 + v * 128 + w];
    }
}

__global__ void k_sp(const float* __restrict__ onehot, int* __restrict__ sp)
{
    int n = blockIdx.x * blockDim.x + threadIdx.x;
    if (n >= NN) return;
    const float* r = onehot + (size_t)n * NSP;
    int best = 0; float bv = r[0];
#pragma unroll
    for (int i = 1; i < NSP; i++) { if (r[i] > bv) { bv = r[i]; best = i; } }
    sp[n] = best;
}

// ------------- projections (4 nodes / block, weights L2-amortized) -------------
__global__ void k_proj_h(const float* __restrict__ nfh,
                         const float* __restrict__ Wh0, const float* __restrict__ Wh1,
                         float* __restrict__ hp0, float* __restrict__ hp1)
{
    int nb = blockIdx.x * 4;
    int v  = threadIdx.x;   // 128
    __shared__ float h0s[4][128];
    __shared__ float h1s[4][384];
    for (int i = v; i < 4 * 512; i += 128) {
        int p = i >> 9, c = i & 511;
        float val = nfh[(size_t)(nb + p) * 512 + c];
        if (c < 128) h0s[p][c] = val; else h1s[p][c - 128] = val;
    }
    __syncthreads();
    float a0[4] = {0, 0, 0, 0};
    float a1[4][3] = {};
    for (int u = 0; u < 128; u++) {
        float w0 = Wh0[u * 128 + v];
        float w1 = Wh1[u * 128 + v];
#pragma unroll
        for (int p = 0; p < 4; p++) {
            a0[p] += h0s[p][u] * w0;
            a1[p][0] += h1s[p][u * 3 + 0] * w1;
            a1[p][1] += h1s[p][u * 3 + 1] * w1;
            a1[p][2] += h1s[p][u * 3 + 2] * w1;
        }
    }
#pragma unroll
    for (int p = 0; p < 4; p++) {
        hp0[(size_t)(nb + p) * 128 + v] = a0[p] * INV_H;
        hp1[(size_t)(nb + p) * 384 + v * 3 + 0] = a1[p][0] * INV_H;
        hp1[(size_t)(nb + p) * 384 + v * 3 + 1] = a1[p][1] * INV_H;
        hp1[(size_t)(nb + p) * 384 + v * 3 + 2] = a1[p][2] * INV_H;
    }
}

__global__ void k_proj_u(const float* __restrict__ nfu,
                         const float* __restrict__ Wu0, const float* __restrict__ Wu1,
                         float* __restrict__ up0, float* __restrict__ up1)
{
    int nb = blockIdx.x * 4;
    int v  = threadIdx.x;   // 64
    __shared__ float u0s[4][64];
    __shared__ float u1s[4][192];
    for (int i = v; i < 4 * 256; i += 64) {
        int p = i >> 8, c = i & 255;
        float val = nfu[(size_t)(nb + p) * 256 + c];
        if (c < 64) u0s[p][c] = val; else u1s[p][c - 64] = val;
    }
    __syncthreads();
    float a0[4] = {0, 0, 0, 0};
    float a1[4][3] = {};
    for (int u = 0; u < 64; u++) {
        float w0 = Wu0[u * 64 + v];
        float w1 = Wu1[u * 64 + v];
#pragma unroll
        for (int p = 0; p < 4; p++) {
            a0[p] += u0s[p][u] * w0;
            a1[p][0] += u1s[p][u * 3 + 0] * w1;
            a1[p][1] += u1s[p][u * 3 + 1] * w1;
            a1[p][2] += u1s[p][u * 3 + 2] * w1;
        }
    }
#pragma unroll
    for (int p = 0; p < 4; p++) {
        up0[(size_t)(nb + p) * 64 + v] = a0[p] * INV_U;
        up1[(size_t)(nb + p) * 192 + v * 3 + 0] = a1[p][0] * INV_U;
        up1[(size_t)(nb + p) * 192 + v * 3 + 1] = a1[p][1] * INV_U;
        up1[(size_t)(nb + p) * 192 + v * 3 + 2] = a1[p][2] * INV_U;
    }
}

// ------------- outer products: A = [xy00 | xy11] -------------
__global__ void k_xy(const float* __restrict__ hp0, const float* __restrict__ up0,
                     const float* __restrict__ hp1, const float* __restrict__ up1,
                     float* __restrict__ A)
{
    int n = blockIdx.x;
    int tid = threadIdx.x;  // 256
    __shared__ float h0s[128], u0s[64], h1s[384], u1s[192];
    if (tid < 128) h0s[tid] = hp0[(size_t)n * 128 + tid];
    else if (tid < 192) u0s[tid - 128] = up0[(size_t)n * 64 + (tid - 128)];
    for (int i = tid; i < 384; i += 256) h1s[i] = hp1[(size_t)n * 384 + i];
    if (tid < 192) u1s[tid] = up1[(size_t)n * 192 + tid];
    __syncthreads();
    float* Ar = A + (size_t)n * 16384;
    for (int c = tid; c < 8192; c += 256) {
        int u = c >> 6, v = c & 63;
        Ar[c] = h0s[u] * u0s[v];
        Ar[c + 8192] = h1s[u * 3 + 0] * u1s[v * 3 + 0]
                     + h1s[u * 3 + 1] * u1s[v * 3 + 1]
                     + h1s[u * 3 + 2] * u1s[v * 3 + 2];
    }
}

// ------------- generic 128x128x8 register-tiled SGEMM with split-K -------------
__global__ __launch_bounds__(256)
void k_sgemm(const float* __restrict__ A, int lda,
             const float* __restrict__ B, int ldb,
             float* __restrict__ C, int ldc,
             int Ktot, size_t partStride)
{
    const int BM = 128, BN = 128, BK = 8, TM = 8, TN = 8;
    const int kLen = Ktot / gridDim.z;
    const int k0b  = blockIdx.z * kLen;
    const int tid = threadIdx.x;
    const int tx = tid & 15;
    const int ty = tid >> 4;
    const int m0 = blockIdx.x * BM;
    const int n0 = blockIdx.y * BN;
    __shared__ __align__(16) float As[BK][BM + 4];
    __shared__ __align__(16) float Bs[BK][BN];
    float acc[TM][TN] = {};
    const int arow = tid >> 1;
    const int acol = (tid & 1) * 4;
    const int brow = tid >> 5;
    const int bcol = (tid & 31) * 4;

    for (int kt = 0; kt < kLen; kt += BK) {
        const int k0 = k0b + kt;
        float4 av = *reinterpret_cast<const float4*>(&A[(size_t)(m0 + arow) * lda + k0 + acol]);
        As[acol + 0][arow] = av.x;
        As[acol + 1][arow] = av.y;
        As[acol + 2][arow] = av.z;
        As[acol + 3][arow] = av.w;
        *reinterpret_cast<float4*>(&Bs[brow][bcol]) =
            *reinterpret_cast<const float4*>(&B[(size_t)(k0 + brow) * ldb + n0 + bcol]);
        __syncthreads();
#pragma unroll
        for (int kk = 0; kk < BK; kk++) {
            float a[TM], b[TN];
            float4 a0 = *reinterpret_cast<const float4*>(&As[kk][ty * TM]);
            float4 a1 = *reinterpret_cast<const float4*>(&As[kk][ty * TM + 4]);
            a[0] = a0.x; a[1] = a0.y; a[2] = a0.z; a[3] = a0.w;
            a[4] = a1.x; a[5] = a1.y; a[6] = a1.z; a[7] = a1.w;
            float4 b0 = *reinterpret_cast<const float4*>(&Bs[kk][tx * TN]);
            float4 b1 = *reinterpret_cast<const float4*>(&Bs[kk][tx * TN + 4]);
            b[0] = b0.x; b[1] = b0.y; b[2] = b0.z; b[3] = b0.w;
            b[4] = b1.x; b[5] = b1.y; b[6] = b1.z; b[7] = b1.w;
#pragma unroll
            for (int i = 0; i < TM; i++)
#pragma unroll
                for (int j = 0; j < TN; j++)
                    acc[i][j] += a[i] * b[j];
        }
        __syncthreads();
    }
    float* Cp = C + (size_t)blockIdx.z * partStride;
#pragma unroll
    for (int i = 0; i < TM; i++) {
#pragma unroll
        for (int j = 0; j < TN; j += 4) {
            float4 v = make_float4(acc[i][j], acc[i][j + 1], acc[i][j + 2], acc[i][j + 3]);
            *reinterpret_cast<float4*>(&Cp[(size_t)(m0 + ty * TM + i) * ldc + n0 + tx * TN + j]) = v;
        }
    }
}

// ------------- z0 split-K reduce + activations -------------
__global__ void k_z0act(const float* __restrict__ P, float* __restrict__ s, float* __restrict__ g)
{
    int idx = blockIdx.x * blockDim.x + threadIdx.x;
    if (idx >= NN * 128) return;
    int n = idx >> 7, w = idx & 127;
    const size_t S = (size_t)NN * 256;
    size_t base = (size_t)n * 256;
    float za = (P[base + w] + P[S + base + w] + P[2 * S + base + w] + P[3 * S + base + w]) * INV_TP;
    float zb = (P[base + 128 + w] + P[S + base + 128 + w] + P[2 * S + base + 128 + w] + P[3 * S + base + 128 + w]) * INV_TP;
    float sa = 1.0f / (1.0f + __expf(-za));
    float sb = 1.0f / (1.0f + __expf(-zb));
    s[idx] = za * sa;
    g[idx] = sb;
}

// ------------- z1 contraction + gate -------------
__global__ void k_z1v(const float* __restrict__ ta, const float* __restrict__ tb,
                      const float* __restrict__ hp1, const float* __restrict__ up1,
                      const float* __restrict__ gg, float* __restrict__ vmat)
{
    int n = blockIdx.x;
    int w = threadIdx.x;   // 128
    __shared__ float u1s[192], h1s[384];
    for (int i = w; i < 192; i += 128) u1s[i] = up1[(size_t)n * 192 + i];
    for (int i = w; i < 384; i += 128) h1s[i] = hp1[(size_t)n * 384 + i];
    __syncthreads();
    float a0 = 0.f, a1 = 0.f, a2 = 0.f;
    const float* tap = ta + (size_t)n * 8192 + w;
    for (int v = 0; v < 64; v++) {
        float t = tap[v * 128];
        a0 += t * u1s[v * 3 + 0];
        a1 += t * u1s[v * 3 + 1];
        a2 += t * u1s[v * 3 + 2];
    }
    const float* tbp = tb + (size_t)n * 16384 + w;
    for (int u = 0; u < 128; u++) {
        float t = tbp[u * 128];
        a0 += t * h1s[u * 3 + 0];
        a1 += t * h1s[u * 3 + 1];
        a2 += t * h1s[u * 3 + 2];
    }
    float gv = gg[(size_t)n * 128 + w];
    vmat[(size_t)n * 384 + w * 3 + 0] = a0 * INV_TP * gv;
    vmat[(size_t)n * 384 + w * 3 + 1] = a1 * INV_TP * gv;
    vmat[(size_t)n * 384 + w * 3 + 2] = a2 * INV_TP * gv;
}

// ------------- y0 = p0 + species term -------------
__global__ void k_y0(const float* __restrict__ s, const float* __restrict__ nfh,
                     const int* __restrict__ sp,
                     const float* __restrict__ Wp0, const float* __restrict__ bp0,
                     const float* __restrict__ Wsc0, float* __restrict__ y0)
{
    int nb = blockIdx.x * 4;
    int w  = threadIdx.x;  // 128
    __shared__ float ss[4][128], h0s[4][128];
    __shared__ int sps[4];
    for (int i = w; i < 512; i += 128) {
        int p = i >> 7, c = i & 127;
        ss[p][c] = s[(size_t)(nb + p) * 128 + c];
        h0s[p][c] = nfh[(size_t)(nb + p) * 512 + c];
    }
    if (w < 4) sps[w] = sp[nb + w];
    __syncthreads();
    float a[4] = {0, 0, 0, 0};
    float b[4] = {0, 0, 0, 0};
    for (int u = 0; u < 128; u++) {
        float wp = Wp0[u * 128 + w];
#pragma unroll
        for (int p = 0; p < 4; p++) a[p] += ss[p][u] * wp;
#pragma unroll
        for (int p = 0; p < 4; p++) b[p] += h0s[p][u] * Wsc0[u * 1280 + sps[p] * 128 + w];
    }
    float bp = bp0[w];
#pragma unroll
    for (int p = 0; p < 4; p++)
        y0[(size_t)(nb + p) * 128 + w] = a[p] * INV_H + bp + b[p] * INV_SC;
}

// ------------- y1 = p1 + species term -------------
__global__ void k_y1(const float* __restrict__ vmat, const float* __restrict__ nfh,
                     const int* __restrict__ sp,
                     const float* __restrict__ Wp1, const float* __restrict__ Wsc1,
                     float* __restrict__ y1)
{
    int nb = blockIdx.x * 2;
    int w  = threadIdx.x;  // 128
    __shared__ float vs[2][384], h1s[2][384];
    __shared__ int sps[2];
    for (int i = w; i < 768; i += 128) {
        int p = i / 384, c = i % 384;
        vs[p][c]  = vmat[(size_t)(nb + p) * 384 + c];
        h1s[p][c] = nfh[(size_t)(nb + p) * 512 + 128 + c];
    }
    if (w < 2) sps[w] = sp[nb + w];
    __syncthreads();
    float a[2][3] = {};
    float b[2][3] = {};
    for (int u = 0; u < 128; u++) {
        float wp = Wp1[u * 128 + w];
#pragma unroll
        for (int p = 0; p < 2; p++) {
            a[p][0] += vs[p][u * 3 + 0] * wp;
            a[p][1] += vs[p][u * 3 + 1] * wp;
            a[p][2] += vs[p][u * 3 + 2] * wp;
        }
#pragma unroll
        for (int p = 0; p < 2; p++) {
            float wsc = Wsc1[u * 1280 + sps[p] * 128 + w];
            b[p][0] += h1s[p][u * 3 + 0] * wsc;
            b[p][1] += h1s[p][u * 3 + 1] * wsc;
            b[p][2] += h1s[p][u * 3 + 2] * wsc;
        }
    }
#pragma unroll
    for (int p = 0; p < 2; p++)
#pragma unroll
        for (int i = 0; i < 3; i++)
            y1[(size_t)(nb + p) * 384 + w * 3 + i] = a[p][i] * INV_H + b[p][i] * INV_SC;
}

// ------------- deterministic group stats -------------
__device__ __forceinline__ int lowerBound(const int* b, int n, int val)
{
    int lo = 0, hi = n;
    while (lo < hi) { int mid = (lo + hi) >> 1; if (b[mid] < val) lo = mid + 1; else hi = mid; }
    return lo;
}

__global__ void k_stats(const float* __restrict__ y0, const float* __restrict__ y1,
                        const int* __restrict__ batch,
                        float* __restrict__ mean0, float* __restrict__ rs0, float* __restrict__ rs1)
{
    int g = blockIdx.x;
    int tid = threadIdx.x;  // 256
    int lo = lowerBound(batch, NN, g);
    int hi = lowerBound(batch, NN, g + 1);
    int cntI = hi - lo;
    float cnt = cntI < 1 ? 1.0f : (float)cntI;
    double s0 = 0.0, q0 = 0.0, q1 = 0.0;
    for (int j = tid; j < cntI * 128; j += 256) {
        float v = y0[(size_t)lo * 128 + j];
        s0 += v; q0 += (double)v * v;
    }
    for (int j = tid; j < cntI * 384; j += 256) {
        float v = y1[(size_t)lo * 384 + j];
        q1 += (double)v * v;
    }
    __shared__ double r0[256], r1[256], r2[256];
    r0[tid] = s0; r1[tid] = q0; r2[tid] = q1;
    __syncthreads();
    for (int off = 128; off > 0; off >>= 1) {
        if (tid < off) { r0[tid] += r0[tid + off]; r1[tid] += r1[tid + off]; r2[tid] += r2[tid + off]; }
        __syncthreads();
    }
    if (tid == 0) {
        double m = r0[0] / ((double)cnt * 128.0);
        double v0 = r1[0] / ((double)cnt * 128.0) - m * m;
        if (v0 < 0.0) v0 = 0.0;
        double v1 = r2[0] / ((double)cnt * 384.0);
        mean0[g] = (float)m;
        rs0[g] = 1.0f / (sqrtf((float)v0) + EPSF);
        rs1[g] = 1.0f / (sqrtf((float)v1) + EPSF);
    }
}

// ------------- final output -------------
__global__ void k_out(const float* __restrict__ nfh, const int* __restrict__ batch,
                      const float* __restrict__ y0, const float* __restrict__ y1,
                      const float* __restrict__ mean0, const float* __restrict__ rs0,
                      const float* __restrict__ rs1,
                      const float* __restrict__ Ws0, const float* __restrict__ bs0,
                      const float* __restrict__ Ws1,
                      const float* __restrict__ lnw0, const float* __restrict__ lnb0,
                      const float* __restrict__ lnw1,
                      float* __restrict__ out)
{
    int nb = blockIdx.x * 2;
    int w  = threadIdx.x;  // 128
    __shared__ float h0s[2][128], h1s[2][384];
    for (int i = w; i < 2 * 512; i += 128) {
        int p = i >> 9, c = i & 511;
        float val = nfh[(size_t)(nb + p) * 512 + c];
        if (c < 128) h0s[p][c] = val; else h1s[p][c - 128] = val;
    }
    __syncthreads();
    float o0[2] = {0, 0};
    float o1[2][3] = {};
    for (int u = 0; u < 128; u++) {
        float w0 = Ws0[u * 128 + w];
        float w1 = Ws1[u * 128 + w];
#pragma unroll
        for (int p = 0; p < 2; p++) {
            o0[p] += h0s[p][u] * w0;
            o1[p][0] += h1s[p][u * 3 + 0] * w1;
            o1[p][1] += h1s[p][u * 3 + 1] * w1;
            o1[p][2] += h1s[p][u * 3 + 2] * w1;
        }
    }
    float lw0 = lnw0[w], lb0 = lnb0[w], lw1 = lnw1[w], bsw = bs0[w];
#pragma unroll
    for (int p = 0; p < 2; p++) {
        int n = nb + p;
        int b = batch[n];
        float m = mean0[b], r0v = rs0[b], r1v = rs1[b];
        out[(size_t)n * 512 + w] =
            (y0[(size_t)n * 128 + w] - m) * r0v * lw0 + lb0 + o0[p] * INV_H + bsw;
#pragma unroll
        for (int i = 0; i < 3; i++)
            out[(size_t)n * 512 + 128 + w * 3 + i] =
                y1[(size_t)n * 384 + w * 3 + i] * r1v * lw1 + o1[p][i] * INV_H;
    }
}

// ------------- host launcher -------------
static void* symAddrOf(const void* sym)
{
    void* p = nullptr;
    cudaGetSymbolAddress(&p, sym);
    return p;
}

extern "C" void kernel_launch(void* const* d_in, const int* in_sizes, int n_in,
                              void* d_out, int out_size)
{
    const float* nfh   = (const float*)d_in[0];
    const float* nfu   = (const float*)d_in[1];
    const float* oneh  = (const float*)d_in[2];
    const int*   batch = (const int*)  d_in[3];
    const float* Wh0   = (const float*)d_in[4];
    const float* Wh1   = (const float*)d_in[5];
    const float* Wu0   = (const float*)d_in[6];
    const float* Wu1   = (const float*)d_in[7];
    const float* Wt00  = (const float*)d_in[8];
    const float* Wt11  = (const float*)d_in[9];
    const float* Wt01  = (const float*)d_in[10];
    const float* Wt10  = (const float*)d_in[11];
    const float* Wp0   = (const float*)d_in[12];
    const float* bp0   = (const float*)d_in[13];
    const float* Wp1   = (const float*)d_in[14];
    const float* Wsc0  = (const float*)d_in[15];
    const float* Wsc1  = (const float*)d_in[16];
    const float* lnw0  = (const float*)d_in[17];
    const float* lnb0  = (const float*)d_in[18];
    const float* lnw1  = (const float*)d_in[19];
    const float* Ws0   = (const float*)d_in[20];
    const float* bs0   = (const float*)d_in[21];
    const float* Ws1   = (const float*)d_in[22];
    float* out = (float*)d_out;

    float* hp0   = (float*)symAddrOf(g_hp0);
    float* hp1   = (float*)symAddrOf(g_hp1);
    float* up0   = (float*)symAddrOf(g_up0);
    float* up1   = (float*)symAddrOf(g_up1);
    float* Amat  = (float*)symAddrOf(g_A);
    float* W0cat = (float*)symAddrOf(g_W0cat);
    float* Wt10t = (float*)symAddrOf(g_Wt10t);
    float* z0p   = (float*)symAddrOf(g_z0p);
    float* sbuf  = (float*)symAddrOf(g_s);
    float* gbuf  = (float*)symAddrOf(g_g);
    float* tabuf = (float*)symAddrOf(g_ta);
    float* tbbuf = (float*)symAddrOf(g_tb);
    float* vmat  = (float*)symAddrOf(g_vmat);
    float* y0buf = (float*)symAddrOf(g_y0);
    float* y1buf = (float*)symAddrOf(g_y1);
    int*   spbuf = (int*)  symAddrOf(g_spi);
    float* mean0 = (float*)symAddrOf(g_mean0);
    float* rs0   = (float*)symAddrOf(g_rs0);
    float* rs1   = (float*)symAddrOf(g_rs1);

    // 1) prep weights (2*8192*256 + 64*16384 = 5,242,880 elems)
    k_prep<<<20480, 256>>>(Wt00, Wt11, Wt10);
    // 2) species indices
    k_sp<<<16, 256>>>(oneh, spbuf);
    // 3) projections
    k_proj_h<<<NN / 4, 128>>>(nfh, Wh0, Wh1, hp0, hp1);
    k_proj_u<<<NN / 4, 64>>>(nfu, Wu0, Wu1, up0, up1);
    // 4) outer products -> A
    k_xy<<<NN, 256>>>(hp0, up0, hp1, up1, Amat);
    // 5) z0 GEMM: (4096x16384)@(16384x256), split-K=4
    {
        dim3 grid(NN / 128, 256 / 128, 4);
        k_sgemm<<<grid, 256>>>(Amat, 16384, W0cat, 256, z0p, 256, 16384, (size_t)NN * 256);
    }
    // 6) z0 reduce + silu/sigmoid
    k_z0act<<<(NN * 128 + 255) / 256, 256>>>(z0p, sbuf, gbuf);
    // 7) ta GEMM: (4096x128)@(128x8192)
    {
        dim3 grid(NN / 128, 8192 / 128, 1);
        k_sgemm<<<grid, 256>>>(hp0, 128, Wt01, 8192, tabuf, 8192, 128, 0);
    }
    // 8) tb GEMM: (4096x64)@(64x16384)
    {
        dim3 grid(NN / 128, 16384 / 128, 1);
        k_sgemm<<<grid, 256>>>(up0, 64, Wt10t, 16384, tbbuf, 16384, 64, 0);
    }
    // 9) z1 + gate
    k_z1v<<<NN, 128>>>(tabuf, tbbuf, hp1, up1, gbuf, vmat);
    // 10) y0, y1
    k_y0<<<NN / 4, 128>>>(sbuf, nfh, spbuf, Wp0, bp0, Wsc0, y0buf);
    k_y1<<<NN / 2, 128>>>(vmat, nfh, spbuf, Wp1, Wsc1, y1buf);
    // 11) group stats
    k_stats<<<NG, 256>>>(y0buf, y1buf, batch, mean0, rs0, rs1);
    // 12) final output
    k_out<<<NN / 2, 128>>>(nfh, batch, y0buf, y1buf, mean0, rs0, rs1,
                           Ws0, bs0, Ws1, lnw0, lnb0, lnw1, out);
}

// round 6
// speedup vs baseline: 1.9902x; 1.9902x over previous
#include <cuda_runtime.h>
#include <cuda_bf16.h>
#include <math.h>

#define NN   4096
#define NG   64
#define NSP  10
#define EPSF 1e-5f
#define INV_H  0.08838834764831845f
#define INV_U  0.125f
#define INV_TP 0.0078125f
#define INV_SC 0.02795084971874737f
#define ISQRT3 0.57735026918962576f

// ---- static scratch ----
static __device__ float g_hp0[NN * 128];
static __device__ float g_hp1[NN * 384];
static __device__ float g_up0[NN * 64];
static __device__ float g_up1[NN * 192];
static __device__ float g_A[(size_t)NN * 16384];
static __device__ unsigned short g_B0h[16384 * 256], g_B0l[16384 * 256];
static __device__ unsigned short g_TAh[128 * 8192],  g_TAl[128 * 8192];
static __device__ unsigned short g_TBh[64 * 16384],  g_TBl[64 * 16384];
static __device__ float g_z0p[(size_t)4 * NN * 256];
static __device__ float g_s[NN * 128];
static __device__ float g_g[NN * 128];
static __device__ float g_ta[(size_t)NN * 8192];
static __device__ float g_tb[(size_t)NN * 16384];
static __device__ float g_vmat[NN * 384];
static __device__ float g_y0[NN * 128];
static __device__ float g_y1[NN * 384];
static __device__ int   g_spi[NN];
static __device__ float g_mean0[NG], g_rs0[NG], g_rs1[NG];

__device__ __forceinline__ void splitbf(float w, unsigned short* h, unsigned short* l)
{
    unsigned hi = (__float_as_uint(w) + 0x8000u) & 0xFFFF0000u;
    *h = (unsigned short)(hi >> 16);
    *l = __bfloat16_as_ushort(__float2bfloat16_rn(w - __uint_as_float(hi)));
}

// ---- prep: split B matrices to bf16 hi/lo ----
__global__ void k_prep(const float* __restrict__ Wt00, const float* __restrict__ Wt11,
                       const float* __restrict__ Wt01, const float* __restrict__ Wt10)
{
    const int S0 = 16384 * 256, S1 = S0 + 128 * 8192, S2 = S1 + 64 * 16384;
    int idx = blockIdx.x * blockDim.x + threadIdx.x;
    if (idx < S0) {
        int k = idx >> 8;
        float w = (k < 8192) ? Wt00[idx] : Wt11[idx - 2097152] * ISQRT3;
        splitbf(w, &g_B0h[idx], &g_B0l[idx]);
    } else if (idx < S1) {
        int j = idx - S0;
        splitbf(Wt01[j], &g_TAh[j], &g_TAl[j]);
    } else if (idx < S2) {
        int j = idx - S1;
        int v = j >> 14, u = (j >> 7) & 127, w = j & 127;
        splitbf(Wt10[(u * 64 + v) * 128 + w], &g_TBh[j], &g_TBl[j]);
    }
}

__global__ void k_sp(const float* __restrict__ onehot, int* __restrict__ sp)
{
    int n = blockIdx.x * blockDim.x + threadIdx.x;
    if (n >= NN) return;
    const float* r = onehot + (size_t)n * NSP;
    int best = 0; float bv = r[0];
#pragma unroll
    for (int i = 1; i < NSP; i++) if (r[i] > bv) { bv = r[i]; best = i; }
    sp[n] = best;
}

// ---- projections ----
__global__ void k_proj_h(const float* __restrict__ nfh,
                         const float* __restrict__ Wh0, const float* __restrict__ Wh1,
                         float* __restrict__ hp0, float* __restrict__ hp1)
{
    int nb = blockIdx.x * 4, v = threadIdx.x;
    __shared__ float h0s[4][128], h1s[4][384];
    for (int i = v; i < 2048; i += 128) {
        int p = i >> 9, c = i & 511;
        float val = nfh[(size_t)(nb + p) * 512 + c];
        if (c < 128) h0s[p][c] = val; else h1s[p][c - 128] = val;
    }
    __syncthreads();
    float a0[4] = {}, a1[4][3] = {};
    for (int u = 0; u < 128; u++) {
        float w0 = Wh0[u * 128 + v], w1 = Wh1[u * 128 + v];
#pragma unroll
        for (int p = 0; p < 4; p++) {
            a0[p] += h0s[p][u] * w0;
            a1[p][0] += h1s[p][u * 3 + 0] * w1;
            a1[p][1] += h1s[p][u * 3 + 1] * w1;
            a1[p][2] += h1s[p][u * 3 + 2] * w1;
        }
    }
#pragma unroll
    for (int p = 0; p < 4; p++) {
        hp0[(size_t)(nb + p) * 128 + v] = a0[p] * INV_H;
#pragma unroll
        for (int i = 0; i < 3; i++)
            hp1[(size_t)(nb + p) * 384 + v * 3 + i] = a1[p][i] * INV_H;
    }
}

__global__ void k_proj_u(const float* __restrict__ nfu,
                         const float* __restrict__ Wu0, const float* __restrict__ Wu1,
                         float* __restrict__ up0, float* __restrict__ up1)
{
    int nb = blockIdx.x * 4, v = threadIdx.x;
    __shared__ float u0s[4][64], u1s[4][192];
    for (int i = v; i < 1024; i += 64) {
        int p = i >> 8, c = i & 255;
        float val = nfu[(size_t)(nb + p) * 256 + c];
        if (c < 64) u0s[p][c] = val; else u1s[p][c - 64] = val;
    }
    __syncthreads();
    float a0[4] = {}, a1[4][3] = {};
    for (int u = 0; u < 64; u++) {
        float w0 = Wu0[u * 64 + v], w1 = Wu1[u * 64 + v];
#pragma unroll
        for (int p = 0; p < 4; p++) {
            a0[p] += u0s[p][u] * w0;
            a1[p][0] += u1s[p][u * 3 + 0] * w1;
            a1[p][1] += u1s[p][u * 3 + 1] * w1;
            a1[p][2] += u1s[p][u * 3 + 2] * w1;
        }
    }
#pragma unroll
    for (int p = 0; p < 4; p++) {
        up0[(size_t)(nb + p) * 64 + v] = a0[p] * INV_U;
#pragma unroll
        for (int i = 0; i < 3; i++)
            up1[(size_t)(nb + p) * 192 + v * 3 + i] = a1[p][i] * INV_U;
    }
}

// ---- outer products -> A ----
__global__ void k_xy(const float* __restrict__ hp0, const float* __restrict__ up0,
                     const float* __restrict__ hp1, const float* __restrict__ up1,
                     float* __restrict__ A)
{
    int n = blockIdx.x, tid = threadIdx.x;
    __shared__ float h0s[128], u0s[64], h1s[384], u1s[192];
    if (tid < 128) h0s[tid] = hp0[(size_t)n * 128 + tid];
    else if (tid < 192) u0s[tid - 128] = up0[(size_t)n * 64 + tid - 128];
    for (int i = tid; i < 384; i += 256) h1s[i] = hp1[(size_t)n * 384 + i];
    if (tid < 192) u1s[tid] = up1[(size_t)n * 192 + tid];
    __syncthreads();
    float* Ar = A + (size_t)n * 16384;
    for (int c = tid; c < 8192; c += 256) {
        int u = c >> 6, v = c & 63;
        Ar[c] = h0s[u] * u0s[v];
        Ar[c + 8192] = h1s[u * 3] * u1s[v * 3] + h1s[u * 3 + 1] * u1s[v * 3 + 1]
                     + h1s[u * 3 + 2] * u1s[v * 3 + 2];
    }
}

// ---- bf16 split tensor-core GEMM: C = A(fp32) @ (Bh+Bl), 128x128x32 tiles ----
#define LDSM4(R, addr) asm volatile( \
    "ldmatrix.sync.aligned.m8n8.x4.shared.b16 {%0,%1,%2,%3}, [%4];" \
    : "=r"((R)[0]), "=r"((R)[1]), "=r"((R)[2]), "=r"((R)[3]) : "r"(addr))
#define LDSM4T(R0,R1,R2,R3, addr) asm volatile( \
    "ldmatrix.sync.aligned.m8n8.x4.trans.shared.b16 {%0,%1,%2,%3}, [%4];" \
    : "=r"(R0), "=r"(R1), "=r"(R2), "=r"(R3) : "r"(addr))
#define MMAB(Cv, Av, Bv) asm volatile( \
    "mma.sync.aligned.m16n8k16.row.col.f32.bf16.bf16.f32 " \
    "{%0,%1,%2,%3},{%4,%5,%6,%7},{%8,%9},{%0,%1,%2,%3};" \
    : "+f"((Cv)[0]), "+f"((Cv)[1]), "+f"((Cv)[2]), "+f"((Cv)[3]) \
    : "r"((Av)[0]), "r"((Av)[1]), "r"((Av)[2]), "r"((Av)[3]), "r"((Bv)[0]), "r"((Bv)[1]))

__global__ __launch_bounds__(256, 2)
void k_mma(const float* __restrict__ A, int lda,
           const unsigned short* __restrict__ Bh, const unsigned short* __restrict__ Bl,
           int ldb, float* __restrict__ C, int ldc, int Ktot, size_t partStride)
{
    __shared__ __align__(16) unsigned short sAh[128][40], sAl[128][40];
    __shared__ __align__(16) unsigned short sBh[32][136], sBl[32][136];
    const int kLen = Ktot / gridDim.z;
    const int kOff = blockIdx.z * kLen;
    const int m0 = blockIdx.x * 128, c0 = blockIdx.y * 128;
    const int tid = threadIdx.x, lane = tid & 31, wid = tid >> 5;
    const int wm = wid & 1, wn = wid >> 1;
    const int ar = tid >> 1, ac = (tid & 1) << 4;

    unsigned aHiB = (unsigned)__cvta_generic_to_shared(&sAh[0][0]);
    unsigned aLoB = (unsigned)__cvta_generic_to_shared(&sAl[0][0]);
    unsigned bHiB = (unsigned)__cvta_generic_to_shared(&sBh[0][0]);
    unsigned bLoB = (unsigned)__cvta_generic_to_shared(&sBl[0][0]);
    unsigned aOff = (unsigned)(((wm * 64 + (lane & 15)) * 40 + (lane >> 4) * 8) * 2);
    unsigned bOff = (unsigned)(((lane & 15) * 136 + wn * 32 + (lane >> 4) * 8) * 2);
    const unsigned aHi = aHiB + aOff, aLo = aLoB + aOff;
    const unsigned bHi = bHiB + bOff, bLo = bLoB + bOff;

    float c[4][4][4];
#pragma unroll
    for (int a = 0; a < 4; a++)
#pragma unroll
        for (int b = 0; b < 4; b++)
#pragma unroll
            for (int d = 0; d < 4; d++) c[a][b][d] = 0.f;

    for (int kt = 0; kt < kLen; kt += 32) {
        const int k0 = kOff + kt;
        // A tile 128x32 fp32 -> split bf16
#pragma unroll
        for (int q = 0; q < 16; q += 4) {
            float4 v = *(const float4*)&A[(size_t)(m0 + ar) * lda + k0 + ac + q];
            unsigned h0 = (__float_as_uint(v.x) + 0x8000u) & 0xFFFF0000u;
            unsigned h1 = (__float_as_uint(v.y) + 0x8000u) & 0xFFFF0000u;
            unsigned h2 = (__float_as_uint(v.z) + 0x8000u) & 0xFFFF0000u;
            unsigned h3 = (__float_as_uint(v.w) + 0x8000u) & 0xFFFF0000u;
            *(unsigned*)&sAh[ar][ac + q]     = (h0 >> 16) | h1;
            *(unsigned*)&sAh[ar][ac + q + 2] = (h2 >> 16) | h3;
            unsigned l01 = (unsigned)__bfloat16_as_ushort(__float2bfloat16_rn(v.x - __uint_as_float(h0)))
                | ((unsigned)__bfloat16_as_ushort(__float2bfloat16_rn(v.y - __uint_as_float(h1))) << 16);
            unsigned l23 = (unsigned)__bfloat16_as_ushort(__float2bfloat16_rn(v.z - __uint_as_float(h2)))
                | ((unsigned)__bfloat16_as_ushort(__float2bfloat16_rn(v.w - __uint_as_float(h3))) << 16);
            *(unsigned*)&sAl[ar][ac + q]     = l01;
            *(unsigned*)&sAl[ar][ac + q + 2] = l23;
        }
        // B tile 32x128 (pre-split)
#pragma unroll
        for (int cb = 0; cb < 2; cb++) {
            int i = tid + (cb << 8);
            int r = i >> 4, c8 = (i & 15) << 3;
            *(uint4*)&sBh[r][c8] = *(const uint4*)&Bh[(size_t)(k0 + r) * ldb + c0 + c8];
            *(uint4*)&sBl[r][c8] = *(const uint4*)&Bl[(size_t)(k0 + r) * ldb + c0 + c8];
        }
        __syncthreads();
#pragma unroll
        for (int kf = 0; kf < 2; kf++) {
            unsigned Af[4][4], Bf[4][2];
#pragma unroll
            for (int mf = 0; mf < 4; mf++) LDSM4(Af[mf], aHi + mf * 1280 + kf * 32);
#pragma unroll
            for (int nq = 0; nq < 2; nq++) {
                unsigned r0, r1, r2, r3;
                LDSM4T(r0, r1, r2, r3, bHi + kf * 4352 + nq * 32);
                Bf[2 * nq][0] = r0; Bf[2 * nq][1] = r1;
                Bf[2 * nq + 1][0] = r2; Bf[2 * nq + 1][1] = r3;
            }
#pragma unroll
            for (int mf = 0; mf < 4; mf++)
#pragma unroll
                for (int nf = 0; nf < 4; nf++) MMAB(c[mf][nf], Af[mf], Bf[nf]);
#pragma unroll
            for (int mf = 0; mf < 4; mf++) LDSM4(Af[mf], aLo + mf * 1280 + kf * 32);
#pragma unroll
            for (int mf = 0; mf < 4; mf++)
#pragma unroll
                for (int nf = 0; nf < 4; nf++) MMAB(c[mf][nf], Af[mf], Bf[nf]);
#pragma unroll
            for (int mf = 0; mf < 4; mf++) LDSM4(Af[mf], aHi + mf * 1280 + kf * 32);
#pragma unroll
            for (int nq = 0; nq < 2; nq++) {
                unsigned r0, r1, r2, r3;
                LDSM4T(r0, r1, r2, r3, bLo + kf * 4352 + nq * 32);
                Bf[2 * nq][0] = r0; Bf[2 * nq][1] = r1;
                Bf[2 * nq + 1][0] = r2; Bf[2 * nq + 1][1] = r3;
            }
#pragma unroll
            for (int mf = 0; mf < 4; mf++)
#pragma unroll
                for (int nf = 0; nf < 4; nf++) MMAB(c[mf][nf], Af[mf], Bf[nf]);
        }
        __syncthreads();
    }
    float* Cp = C + (size_t)blockIdx.z * partStride;
    int gq = lane >> 2, t4 = lane & 3;
#pragma unroll
    for (int mf = 0; mf < 4; mf++)
#pragma unroll
        for (int nf = 0; nf < 4; nf++) {
            int row = m0 + wm * 64 + mf * 16 + gq;
            int col = c0 + wn * 32 + nf * 8 + t4 * 2;
            *(float2*)&Cp[(size_t)row * ldc + col] = make_float2(c[mf][nf][0], c[mf][nf][1]);
            *(float2*)&Cp[(size_t)(row + 8) * ldc + col] = make_float2(c[mf][nf][2], c[mf][nf][3]);
        }
}

// ---- z0 reduce + activations ----
__global__ void k_z0act(const float* __restrict__ P, float* __restrict__ s, float* __restrict__ g)
{
    int idx = blockIdx.x * blockDim.x + threadIdx.x;
    if (idx >= NN * 128) return;
    int n = idx >> 7, w = idx & 127;
    const size_t S = (size_t)NN * 256;
    size_t base = (size_t)n * 256;
    float za = (P[base + w] + P[S + base + w] + P[2 * S + base + w] + P[3 * S + base + w]) * INV_TP;
    float zb = (P[base + 128 + w] + P[S + base + 128 + w] + P[2 * S + base + 128 + w] + P[3 * S + base + 128 + w]) * INV_TP;
    s[idx] = za / (1.0f + __expf(-za));
    g[idx] = 1.0f / (1.0f + __expf(-zb));
}

// ---- z1 + gate ----
__global__ void k_z1v(const float* __restrict__ ta, const float* __restrict__ tb,
                      const float* __restrict__ hp1, const float* __restrict__ up1,
                      const float* __restrict__ gg, float* __restrict__ vmat)
{
    int n = blockIdx.x, w = threadIdx.x;
    __shared__ float u1s[192], h1s[384];
    for (int i = w; i < 192; i += 128) u1s[i] = up1[(size_t)n * 192 + i];
    for (int i = w; i < 384; i += 128) h1s[i] = hp1[(size_t)n * 384 + i];
    __syncthreads();
    float a0 = 0.f, a1 = 0.f, a2 = 0.f;
    const float* tap = ta + (size_t)n * 8192 + w;
    for (int v = 0; v < 64; v++) {
        float t = tap[v * 128];
        a0 += t * u1s[v * 3]; a1 += t * u1s[v * 3 + 1]; a2 += t * u1s[v * 3 + 2];
    }
    const float* tbp = tb + (size_t)n * 16384 + w;
    for (int u = 0; u < 128; u++) {
        float t = tbp[u * 128];
        a0 += t * h1s[u * 3]; a1 += t * h1s[u * 3 + 1]; a2 += t * h1s[u * 3 + 2];
    }
    float gv = gg[(size_t)n * 128 + w];
    vmat[(size_t)n * 384 + w * 3 + 0] = a0 * INV_TP * gv;
    vmat[(size_t)n * 384 + w * 3 + 1] = a1 * INV_TP * gv;
    vmat[(size_t)n * 384 + w * 3 + 2] = a2 * INV_TP * gv;
}

// ---- y0 ----
__global__ void k_y0(const float* __restrict__ s, const float* __restrict__ nfh,
                     const int* __restrict__ sp, const float* __restrict__ Wp0,
                     const float* __restrict__ bp0, const float* __restrict__ Wsc0,
                     float* __restrict__ y0)
{
    int nb = blockIdx.x * 4, w = threadIdx.x;
    __shared__ float ss[4][128], h0s[4][128];
    __shared__ int sps[4];
    for (int i = w; i < 512; i += 128) {
        int p = i >> 7, c = i & 127;
        ss[p][c] = s[(size_t)(nb + p) * 128 + c];
        h0s[p][c] = nfh[(size_t)(nb + p) * 512 + c];
    }
    if (w < 4) sps[w] = sp[nb + w];
    __syncthreads();
    float a[4] = {}, b[4] = {};
    for (int u = 0; u < 128; u++) {
        float wp = Wp0[u * 128 + w];
#pragma unroll
        for (int p = 0; p < 4; p++) a[p] += ss[p][u] * wp;
#pragma unroll
        for (int p = 0; p < 4; p++) b[p] += h0s[p][u] * Wsc0[u * 1280 + sps[p] * 128 + w];
    }
    float bp = bp0[w];
#pragma unroll
    for (int p = 0; p < 4; p++)
        y0[(size_t)(nb + p) * 128 + w] = a[p] * INV_H + bp + b[p] * INV_SC;
}

// ---- y1 ----
__global__ void k_y1(const float* __restrict__ vmat, const float* __restrict__ nfh,
                     const int* __restrict__ sp, const float* __restrict__ Wp1,
                     const float* __restrict__ Wsc1, float* __restrict__ y1)
{
    int nb = blockIdx.x * 2, w = threadIdx.x;
    __shared__ float vs[2][384], h1s[2][384];
    __shared__ int sps[2];
    for (int i = w; i < 768; i += 128) {
        int p = i / 384, c = i % 384;
        vs[p][c] = vmat[(size_t)(nb + p) * 384 + c];
        h1s[p][c] = nfh[(size_t)(nb + p) * 512 + 128 + c];
    }
    if (w < 2) sps[w] = sp[nb + w];
    __syncthreads();
    float a[2][3] = {}, b[2][3] = {};
    for (int u = 0; u < 128; u++) {
        float wp = Wp1[u * 128 + w];
#pragma unroll
        for (int p = 0; p < 2; p++) {
            a[p][0] += vs[p][u * 3] * wp;
            a[p][1] += vs[p][u * 3 + 1] * wp;
            a[p][2] += vs[p][u * 3 + 2] * wp;
        }
#pragma unroll
        for (int p = 0; p < 2; p++) {
            float wsc = Wsc1[u * 1280 + sps[p] * 128 + w];
            b[p][0] += h1s[p][u * 3] * wsc;
            b[p][1] += h1s[p][u * 3 + 1] * wsc;
            b[p][2] += h1s[p][u * 3 + 2] * wsc;
        }
    }
#pragma unroll
    for (int p = 0; p < 2; p++)
#pragma unroll
        for (int i = 0; i < 3; i++)
            y1[(size_t)(nb + p) * 384 + w * 3 + i] = a[p][i] * INV_H + b[p][i] * INV_SC;
}

// ---- deterministic group stats ----
__device__ __forceinline__ int lowerBound(const int* b, int n, int val)
{
    int lo = 0, hi = n;
    while (lo < hi) { int mid = (lo + hi) >> 1; if (b[mid] < val) lo = mid + 1; else hi = mid; }
    return lo;
}

__global__ void k_stats(const float* __restrict__ y0, const float* __restrict__ y1,
                        const int* __restrict__ batch,
                        float* __restrict__ mean0, float* __restrict__ rs0, float* __restrict__ rs1)
{
    int g = blockIdx.x, tid = threadIdx.x;
    int lo = lowerBound(batch, NN, g);
    int hi = lowerBound(batch, NN, g + 1);
    int cntI = hi - lo;
    float cnt = cntI < 1 ? 1.0f : (float)cntI;
    double s0 = 0.0, q0 = 0.0, q1 = 0.0;
    for (int j = tid; j < cntI * 128; j += 256) {
        float v = y0[(size_t)lo * 128 + j];
        s0 += v; q0 += (double)v * v;
    }
    for (int j = tid; j < cntI * 384; j += 256) {
        float v = y1[(size_t)lo * 384 + j];
        q1 += (double)v * v;
    }
    __shared__ double r0[256], r1[256], r2[256];
    r0[tid] = s0; r1[tid] = q0; r2[tid] = q1;
    __syncthreads();
    for (int off = 128; off > 0; off >>= 1) {
        if (tid < off) { r0[tid] += r0[tid + off]; r1[tid] += r1[tid + off]; r2[tid] += r2[tid + off]; }
        __syncthreads();
    }
    if (tid == 0) {
        double m = r0[0] / ((double)cnt * 128.0);
        double v0 = r1[0] / ((double)cnt * 128.0) - m * m;
        if (v0 < 0.0) v0 = 0.0;
        double v1 = r2[0] / ((double)cnt * 384.0);
        mean0[g] = (float)m;
        rs0[g] = 1.0f / (sqrtf((float)v0) + EPSF);
        rs1[g] = 1.0f / (sqrtf((float)v1) + EPSF);
    }
}

// ---- final output ----
__global__ void k_out(const float* __restrict__ nfh, const int* __restrict__ batch,
                      const float* __restrict__ y0, const float* __restrict__ y1,
                      const float* __restrict__ mean0, const float* __restrict__ rs0,
                      const float* __restrict__ rs1,
                      const float* __restrict__ Ws0, const float* __restrict__ bs0,
                      const float* __restrict__ Ws1,
                      const float* __restrict__ lnw0, const float* __restrict__ lnb0,
                      const float* __restrict__ lnw1, float* __restrict__ out)
{
    int nb = blockIdx.x * 2, w = threadIdx.x;
    __shared__ float h0s[2][128], h1s[2][384];
    for (int i = w; i < 1024; i += 128) {
        int p = i >> 9, c = i & 511;
        float val = nfh[(size_t)(nb + p) * 512 + c];
        if (c < 128) h0s[p][c] = val; else h1s[p][c - 128] = val;
    }
    __syncthreads();
    float o0[2] = {}, o1[2][3] = {};
    for (int u = 0; u < 128; u++) {
        float w0 = Ws0[u * 128 + w], w1 = Ws1[u * 128 + w];
#pragma unroll
        for (int p = 0; p < 2; p++) {
            o0[p] += h0s[p][u] * w0;
            o1[p][0] += h1s[p][u * 3] * w1;
            o1[p][1] += h1s[p][u * 3 + 1] * w1;
            o1[p][2] += h1s[p][u * 3 + 2] * w1;
        }
    }
    float lw0 = lnw0[w], lb0 = lnb0[w], lw1 = lnw1[w], bsw = bs0[w];
#pragma unroll
    for (int p = 0; p < 2; p++) {
        int n = nb + p, b = batch[n];
        float m = mean0[b], r0v = rs0[b], r1v = rs1[b];
        out[(size_t)n * 512 + w] =
            (y0[(size_t)n * 128 + w] - m) * r0v * lw0 + lb0 + o0[p] * INV_H + bsw;
#pragma unroll
        for (int i = 0; i < 3; i++)
            out[(size_t)n * 512 + 128 + w * 3 + i] =
                y1[(size_t)n * 384 + w * 3 + i] * r1v * lw1 + o1[p][i] * INV_H;
    }
}

// ---- host launcher ----
static void* sym(const void* s) { void* p = nullptr; cudaGetSymbolAddress(&p, s); return p; }

extern "C" void kernel_launch(void* const* d_in, const int* in_sizes, int n_in,
                              void* d_out, int out_size)
{
    const float* nfh  = (const float*)d_in[0];
    const float* nfu  = (const float*)d_in[1];
    const float* oneh = (const float*)d_in[2];
    const int* batch  = (const int*)d_in[3];
    const float* Wh0  = (const float*)d_in[4];
    const float* Wh1  = (const float*)d_in[5];
    const float* Wu0  = (const float*)d_in[6];
    const float* Wu1  = (const float*)d_in[7];
    const float* Wt00 = (const float*)d_in[8];
    const float* Wt11 = (const float*)d_in[9];
    const float* Wt01 = (const float*)d_in[10];
    const float* Wt10 = (const float*)d_in[11];
    const float* Wp0  = (const float*)d_in[12];
    const float* bp0  = (const float*)d_in[13];
    const float* Wp1  = (const float*)d_in[14];
    const float* Wsc0 = (const float*)d_in[15];
    const float* Wsc1 = (const float*)d_in[16];
    const float* lnw0 = (const float*)d_in[17];
    const float* lnb0 = (const float*)d_in[18];
    const float* lnw1 = (const float*)d_in[19];
    const float* Ws0  = (const float*)d_in[20];
    const float* bs0  = (const float*)d_in[21];
    const float* Ws1  = (const float*)d_in[22];
    float* out = (float*)d_out;

    float* hp0  = (float*)sym(g_hp0);
    float* hp1  = (float*)sym(g_hp1);
    float* up0  = (float*)sym(g_up0);
    float* up1  = (float*)sym(g_up1);
    float* Amat = (float*)sym(g_A);
    unsigned short* B0h = (unsigned short*)sym(g_B0h);
    unsigned short* B0l = (unsigned short*)sym(g_B0l);
    unsigned short* TAh = (unsigned short*)sym(g_TAh);
    unsigned short* TAl = (unsigned short*)sym(g_TAl);
    unsigned short* TBh = (unsigned short*)sym(g_TBh);
    unsigned short* TBl = (unsigned short*)sym(g_TBl);
    float* z0p  = (float*)sym(g_z0p);
    float* sbuf = (float*)sym(g_s);
    float* gbuf = (float*)sym(g_g);
    float* tab  = (float*)sym(g_ta);
    float* tbb  = (float*)sym(g_tb);
    float* vmat = (float*)sym(g_vmat);
    float* y0b  = (float*)sym(g_y0);
    float* y1b  = (float*)sym(g_y1);
    int*   spb  = (int*)sym(g_spi);
    float* mean0 = (float*)sym(g_mean0);
    float* rs0  = (float*)sym(g_rs0);
    float* rs1  = (float*)sym(g_rs1);

    k_prep<<<24576, 256>>>(Wt00, Wt11, Wt01, Wt10);
    k_sp<<<16, 256>>>(oneh, spb);
    k_proj_h<<<NN / 4, 128>>>(nfh, Wh0, Wh1, hp0, hp1);
    k_proj_u<<<NN / 4, 64>>>(nfu, Wu0, Wu1, up0, up1);
    k_xy<<<NN, 256>>>(hp0, up0, hp1, up1, Amat);
    {   // z0: (4096x16384)@(16384x256), split-K=4
        dim3 grid(32, 2, 4);
        k_mma<<<grid, 256>>>(Amat, 16384, B0h, B0l, 256, z0p, 256, 16384, (size_t)NN * 256);
    }
    k_z0act<<<(NN * 128 + 255) / 256, 256>>>(z0p, sbuf, gbuf);
    {   // ta: (4096x128)@(128x8192)
        dim3 grid(32, 64, 1);
        k_mma<<<grid, 256>>>(hp0, 128, TAh, TAl, 8192, tab, 8192, 128, 0);
    }
    {   // tb: (4096x64)@(64x16384)
        dim3 grid(32, 128, 1);
        k_mma<<<grid, 256>>>(up0, 64, TBh, TBl, 16384, tbb, 16384, 64, 0);
    }
    k_z1v<<<NN, 128>>>(tab, tbb, hp1, up1, gbuf, vmat);
    k_y0<<<NN / 4, 128>>>(sbuf, nfh, spb, Wp0, bp0, Wsc0, y0b);
    k_y1<<<NN / 2, 128>>>(vmat, nfh, spb, Wp1, Wsc1, y1b);
    k_stats<<<NG, 256>>>(y0b, y1b, batch, mean0, rs0, rs1);
    k_out<<<NN / 2, 128>>>(nfh, batch, y0b, y1b, mean0, rs0, rs1,
                           Ws0, bs0, Ws1, lnw0, lnb0, lnw1, out);
}